// round 1
// baseline (speedup 1.0000x reference)
#include <cuda_runtime.h>
#include <cuda_fp16.h>
#include <stdint.h>

// Problem constants
#define Vn    10000
#define Dn    300
#define Bn    64
#define Ln    128
#define KPn   10016   // K padded to multiple of 32
#define NPn   384     // N padded to 3 x 128 tiles
#define MMAXn 8192    // worst-case unique concepts (B*L)

// ---- device scratch (allocation-free: module globals, zero-init .bss) ----
__device__ __half g_P[(size_t)MMAXn * KPn];   // probs, fp16  (~164 MB, only U rows touched)
__device__ __half g_W16[(size_t)KPn * NPn];   // concept_w fp16, padded with zeros
__device__ float  g_G[(size_t)MMAXn * NPn];   // per-unique-concept output rows
__device__ float  g_ps[Bn * Dn];              // per-sample means
__device__ float  g_ctx[Dn];
__device__ float  g_cn;
__device__ float  g_cosv[Vn];
__device__ int    g_slot[Vn];
__device__ int    g_uniq[MMAXn];
__device__ int    g_cnt;

// ------------------------------------------------------------------ reset
__global__ void k_reset() {
    int i = blockIdx.x * blockDim.x + threadIdx.x;
    if (i < Vn) g_slot[i] = -1;
    if (i == 0) g_cnt = 0;
}

// ------------------------------------------------- context: per-sample means
__global__ void k_context(const int* __restrict__ clist,
                          const int* __restrict__ clen,
                          const float* __restrict__ embed) {
    int b = blockIdx.x;
    int d = threadIdx.x;
    if (d >= Dn) return;
    int len = clen[b];
    float acc = 0.f;
    for (int l = 0; l < len; l++) {
        int c = clist[b * Ln + l];
        acc += embed[(size_t)c * Dn + d];
    }
    float den = (float)(len > 0 ? len : 1);
    g_ps[b * Dn + d] = acc / den;
}

// -------------------------------------- finalize: context mean + its norm
__global__ void k_finalize() {   // 1 block, 320 threads (deterministic order)
    int d = threadIdx.x;
    float c = 0.f;
    if (d < Dn) {
        float s = 0.f;
        for (int b = 0; b < Bn; b++) s += g_ps[b * Dn + d];
        c = s * (1.f / Bn);
        g_ctx[d] = c;
    }
    float sq = c * c;
    __shared__ float red[10];
    #pragma unroll
    for (int o = 16; o > 0; o >>= 1) sq += __shfl_xor_sync(0xffffffffu, sq, o);
    if ((threadIdx.x & 31) == 0) red[threadIdx.x >> 5] = sq;
    __syncthreads();
    if (threadIdx.x == 0) {
        float t = 0.f;
        for (int w = 0; w < 10; w++) t += red[w];
        g_cn = sqrtf(t);
    }
}

// -------------------------------------------- dedup active concept ids
__global__ void k_dedup(const int* __restrict__ clist,
                        const int* __restrict__ clen) {
    int b = blockIdx.x;
    int l = threadIdx.x;
    if (l >= clen[b]) return;
    int c = clist[b * Ln + l];
    if (atomicCAS(&g_slot[c], -1, -2) == -1) {
        int idx = atomicAdd(&g_cnt, 1);
        g_uniq[idx] = c;
        g_slot[c]   = idx;   // visible at kernel boundary
    }
}

// ------------------ cosine sims + fp16 conversion of concept_w (one warp/row)
__global__ void k_cosw(const float* __restrict__ cw) {
    int v = (blockIdx.x << 3) + (threadIdx.x >> 5);
    if (v >= Vn) return;
    int lane = threadIdx.x & 31;
    const float* row = cw + (size_t)v * Dn;
    __half* wrow = g_W16 + (size_t)v * NPn;
    float dot = 0.f, rn2 = 0.f;
    for (int d = lane; d < Dn; d += 32) {
        float w = row[d];
        dot += w * g_ctx[d];
        rn2 += w * w;
        wrow[d] = __float2half(w);
    }
    #pragma unroll
    for (int o = 16; o > 0; o >>= 1) {
        dot += __shfl_xor_sync(0xffffffffu, dot, o);
        rn2 += __shfl_xor_sync(0xffffffffu, rn2, o);
    }
    if (lane == 0) {
        float den = fmaxf(g_cn * sqrtf(rn2), 1e-8f);
        g_cosv[v] = fabsf(dot) / den;
    }
}

// -------------------------- per-unique-concept weights + softmax -> fp16 P row
__global__ __launch_bounds__(256) void k_probs(const float* __restrict__ edge,
                                               const float* __restrict__ aff,
                                               const float* __restrict__ lam) {
    __shared__ float sw[Vn];
    __shared__ float red[9];
    int u = blockIdx.x;
    if (u >= g_cnt) return;
    int c = g_uniq[u];
    const float* em = edge + (size_t)c * Vn;
    int t = threadIdx.x;

    float m = -3.4e38f;
    for (int v = t; v < Vn; v += 256) {
        float e  = em[v];
        float lv = lam[v];
        float w  = lv * e * g_cosv[v] + (1.f - lv) * aff[v] * (e > 0.f ? 1.f : 0.f);
        w *= 5.0f;                     // CF
        sw[v] = w;
        m = fmaxf(m, w);
    }
    #pragma unroll
    for (int o = 16; o > 0; o >>= 1) m = fmaxf(m, __shfl_xor_sync(0xffffffffu, m, o));
    if ((t & 31) == 0) red[t >> 5] = m;
    __syncthreads();
    if (t < 32) {
        float x = (t < 8) ? red[t] : -3.4e38f;
        #pragma unroll
        for (int o = 4; o > 0; o >>= 1) x = fmaxf(x, __shfl_xor_sync(0xffffffffu, x, o));
        if (t == 0) red[8] = x;
    }
    __syncthreads();
    m = red[8];

    float s = 0.f;
    for (int v = t; v < Vn; v += 256) {
        float e = __expf(sw[v] - m);
        sw[v] = e;
        s += e;
    }
    __syncthreads();   // everyone read red[8]; safe to reuse
    #pragma unroll
    for (int o = 16; o > 0; o >>= 1) s += __shfl_xor_sync(0xffffffffu, s, o);
    if ((t & 31) == 0) red[t >> 5] = s;
    __syncthreads();
    if (t < 32) {
        float x = (t < 8) ? red[t] : 0.f;
        #pragma unroll
        for (int o = 4; o > 0; o >>= 1) x += __shfl_xor_sync(0xffffffffu, x, o);
        if (t == 0) red[8] = x;
    }
    __syncthreads();
    float inv = 1.f / red[8];

    __half* pr = g_P + (size_t)u * KPn;
    for (int v = t; v < Vn; v += 256) pr[v] = __float2half(sw[v] * inv);
    // P pad cols [Vn, KPn) stay zero from .bss — never written, contribute 0
}

// ---------------------------------------------------------------- GEMM
// C[U,384] = P[U,10016]fp16 @ W16[10016,384]fp16, fp32 accumulate
// CTA tile 64x128, k-tile 32, 8 warps (2x4), warp tile 32x32, mma m16n8k16
__device__ __forceinline__ void cpa16(void* s, const void* g) {
    unsigned a = (unsigned)__cvta_generic_to_shared(s);
    asm volatile("cp.async.ca.shared.global [%0], [%1], 16;\n" :: "r"(a), "l"(g));
}

__global__ __launch_bounds__(256) void k_gemm() {
    __shared__ __half As[2][64][40];    // pad 40 -> conflict-free ldmatrix
    __shared__ __half Bs[2][32][136];   // pad 136
    int cnt = g_cnt;
    int gm0 = blockIdx.x * 64;
    if (gm0 >= cnt) return;
    int n0 = blockIdx.y * 128;
    int t = threadIdx.x;
    int lane = t & 31, wid = t >> 5;
    int wm = (wid >> 2) * 32, wn = (wid & 3) * 32;

    float acc[2][4][4];
    #pragma unroll
    for (int i = 0; i < 2; i++)
        #pragma unroll
        for (int j = 0; j < 4; j++)
            #pragma unroll
            for (int k = 0; k < 4; k++) acc[i][j][k] = 0.f;

    // A tile 64x32 halves = 256 x 16B chunks (1/thread)
    int arow = t >> 2, acol = (t & 3) * 8;
    const __half* gA = g_P + (size_t)(gm0 + arow) * KPn + acol;
    // B tile 32x128 halves = 512 chunks (2/thread)
    int brow = t >> 4, bcol = (t & 15) * 8;
    const __half* gB = g_W16 + (size_t)brow * NPn + n0 + bcol;

    const int KT = KPn / 32;   // 313, exact

    #define LOADT(kt, bfv) {                                             \
        cpa16(&As[bfv][arow][acol], gA + (size_t)(kt) * 32);             \
        cpa16(&Bs[bfv][brow][bcol],     gB + (size_t)(kt) * 32 * NPn);   \
        cpa16(&Bs[bfv][brow + 16][bcol],                                 \
              gB + (size_t)((kt) * 32 + 16) * NPn);                      \
        asm volatile("cp.async.commit_group;\n"); }

    LOADT(0, 0);
    int bf = 0;
    for (int kt = 0; kt < KT; kt++) {
        if (kt + 1 < KT) {
            LOADT(kt + 1, bf ^ 1);
            asm volatile("cp.async.wait_group 1;\n");
        } else {
            asm volatile("cp.async.wait_group 0;\n");
        }
        __syncthreads();
        #pragma unroll
        for (int kk = 0; kk < 32; kk += 16) {
            uint32_t a[2][4];
            #pragma unroll
            for (int mi = 0; mi < 2; mi++) {
                unsigned ad = (unsigned)__cvta_generic_to_shared(
                    &As[bf][wm + mi * 16 + (lane & 15)][kk + (lane >> 4) * 8]);
                asm volatile("ldmatrix.sync.aligned.m8n8.x4.shared.b16 {%0,%1,%2,%3}, [%4];\n"
                    : "=r"(a[mi][0]), "=r"(a[mi][1]), "=r"(a[mi][2]), "=r"(a[mi][3])
                    : "r"(ad));
            }
            uint32_t bb[4][2];
            #pragma unroll
            for (int nh = 0; nh < 2; nh++) {
                unsigned ad = (unsigned)__cvta_generic_to_shared(
                    &Bs[bf][kk + (lane & 15)][wn + nh * 16 + (lane >> 4) * 8]);
                asm volatile("ldmatrix.sync.aligned.m8n8.x4.trans.shared.b16 {%0,%1,%2,%3}, [%4];\n"
                    : "=r"(bb[nh * 2][0]), "=r"(bb[nh * 2][1]),
                      "=r"(bb[nh * 2 + 1][0]), "=r"(bb[nh * 2 + 1][1])
                    : "r"(ad));
            }
            #pragma unroll
            for (int mi = 0; mi < 2; mi++)
                #pragma unroll
                for (int nj = 0; nj < 4; nj++)
                    asm volatile("mma.sync.aligned.m16n8k16.row.col.f32.f16.f16.f32 "
                        "{%0,%1,%2,%3},{%4,%5,%6,%7},{%8,%9},{%0,%1,%2,%3};\n"
                        : "+f"(acc[mi][nj][0]), "+f"(acc[mi][nj][1]),
                          "+f"(acc[mi][nj][2]), "+f"(acc[mi][nj][3])
                        : "r"(a[mi][0]), "r"(a[mi][1]), "r"(a[mi][2]), "r"(a[mi][3]),
                          "r"(bb[nj][0]), "r"(bb[nj][1]));
        }
        __syncthreads();
        bf ^= 1;
    }
    #undef LOADT

    #pragma unroll
    for (int mi = 0; mi < 2; mi++) {
        int r0 = gm0 + wm + mi * 16 + (lane >> 2);
        #pragma unroll
        for (int nj = 0; nj < 4; nj++) {
            int cc = n0 + wn + nj * 8 + (lane & 3) * 2;
            g_G[(size_t)r0 * NPn + cc]           = acc[mi][nj][0];
            g_G[(size_t)r0 * NPn + cc + 1]       = acc[mi][nj][1];
            g_G[(size_t)(r0 + 8) * NPn + cc]     = acc[mi][nj][2];
            g_G[(size_t)(r0 + 8) * NPn + cc + 1] = acc[mi][nj][3];
        }
    }
}

// ----------------------------------------------- gather + masked mean
__global__ void k_out(const int* __restrict__ clist,
                      const int* __restrict__ clen,
                      float* __restrict__ out) {
    int b = blockIdx.x;
    int d = threadIdx.x;
    if (d >= Dn) return;
    int len = clen[b];
    float acc = 0.f;
    for (int l = 0; l < len; l++) {
        int c = clist[b * Ln + l];
        int s = g_slot[c];
        acc += g_G[(size_t)s * NPn + d];
    }
    float den = (float)(len > 0 ? len : 1);
    out[b * Dn + d] = acc / den;
}

// ------------------------------------------------------------------ launch
extern "C" void kernel_launch(void* const* d_in, const int* in_sizes, int n_in,
                              void* d_out, int out_size) {
    const int*   clist = (const int*)d_in[0];
    const int*   clen  = (const int*)d_in[1];
    const float* embed = (const float*)d_in[2];
    const float* cw    = (const float*)d_in[3];
    const float* edge  = (const float*)d_in[4];
    const float* aff   = (const float*)d_in[5];
    const float* lam   = (const float*)d_in[6];
    float* out = (float*)d_out;

    k_reset<<<(Vn + 255) / 256, 256>>>();
    k_context<<<Bn, 320>>>(clist, clen, embed);
    k_finalize<<<1, 320>>>();
    k_dedup<<<Bn, Ln>>>(clist, clen);
    k_cosw<<<(Vn + 7) / 8, 256>>>(cw);
    k_probs<<<MMAXn, 256>>>(edge, aff, lam);
    dim3 gg(MMAXn / 64, NPn / 128);
    k_gemm<<<gg, 256>>>();
    k_out<<<Bn, 320>>>(clist, clen, out);
}

// round 3
// speedup vs baseline: 1.5284x; 1.5284x over previous
#include <cuda_runtime.h>
#include <cuda_fp16.h>
#include <stdint.h>

// Problem constants
#define Vn    10000
#define Dn    300
#define Bn    64
#define Ln    128
#define KPn   10016   // K padded to multiple of 32
#define NPn   320     // N padded to 5 x 64 tiles
#define MMAXn 8192    // worst-case unique concepts (B*L)

// ---- device scratch (allocation-free module globals) ----
__device__ __half g_P[(size_t)MMAXn * KPn];   // probs fp16 (only cnt rows live)
__device__ __half g_W16[(size_t)KPn * NPn];   // concept_w fp16, zero-padded
__device__ float  g_G[(size_t)MMAXn * NPn];   // per-unique-concept output rows
__device__ float  g_ps[Bn * Dn];
__device__ float  g_ctx[Dn];
__device__ float  g_cn;
__device__ float2 g_ab[Vn];                   // (5*lam*cos, 5*(1-lam)*aff)
__device__ int    g_slot[Vn];
__device__ int    g_uniq[MMAXn];
__device__ int    g_cnt;

// ------------------------------------------------------------------ reset
__global__ void k_reset() {
    int i = blockIdx.x * blockDim.x + threadIdx.x;
    if (i < Vn) g_slot[i] = -1;
    if (i == 0) g_cnt = 0;
}

// ------------------------------------------------- context: per-sample means
__global__ void k_context(const int* __restrict__ clist,
                          const int* __restrict__ clen,
                          const float* __restrict__ embed) {
    int b = blockIdx.x;
    int d = threadIdx.x;
    if (d >= Dn) return;
    int len = clen[b];
    float acc = 0.f;
    for (int l = 0; l < len; l++) {
        int c = clist[b * Ln + l];
        acc += embed[(size_t)c * Dn + d];
    }
    float den = (float)(len > 0 ? len : 1);
    g_ps[b * Dn + d] = acc / den;
}

// -------------------------------------- finalize: context mean + its norm
__global__ void k_finalize() {   // 1 block, 320 threads
    int d = threadIdx.x;
    float c = 0.f;
    if (d < Dn) {
        float s = 0.f;
        for (int b = 0; b < Bn; b++) s += g_ps[b * Dn + d];
        c = s * (1.f / Bn);
        g_ctx[d] = c;
    }
    float sq = c * c;
    __shared__ float red[10];
    #pragma unroll
    for (int o = 16; o > 0; o >>= 1) sq += __shfl_xor_sync(0xffffffffu, sq, o);
    if ((threadIdx.x & 31) == 0) red[threadIdx.x >> 5] = sq;
    __syncthreads();
    if (threadIdx.x == 0) {
        float t = 0.f;
        for (int w = 0; w < 10; w++) t += red[w];
        g_cn = sqrtf(t);
    }
}

// -------------------------------------------- dedup active concept ids
__global__ void k_dedup(const int* __restrict__ clist,
                        const int* __restrict__ clen) {
    int b = blockIdx.x;
    int l = threadIdx.x;
    if (l >= clen[b]) return;
    int c = clist[b * Ln + l];
    if (atomicCAS(&g_slot[c], -1, -2) == -1) {
        int idx = atomicAdd(&g_cnt, 1);
        g_uniq[idx] = c;
        g_slot[c]   = idx;
    }
}

// --------- cosine sims -> (a,b) coeffs + fp16 conversion of concept_w
__global__ void k_cosw(const float* __restrict__ cw,
                       const float* __restrict__ aff,
                       const float* __restrict__ lam) {
    int v = (blockIdx.x << 3) + (threadIdx.x >> 5);
    if (v >= Vn) return;
    int lane = threadIdx.x & 31;
    const float* row = cw + (size_t)v * Dn;
    __half* wrow = g_W16 + (size_t)v * NPn;
    float dot = 0.f, rn2 = 0.f;
    for (int d = lane; d < Dn; d += 32) {
        float w = row[d];
        dot += w * g_ctx[d];
        rn2 += w * w;
        wrow[d] = __float2half(w);
    }
    #pragma unroll
    for (int o = 16; o > 0; o >>= 1) {
        dot += __shfl_xor_sync(0xffffffffu, dot, o);
        rn2 += __shfl_xor_sync(0xffffffffu, rn2, o);
    }
    if (lane == 0) {
        float den = fmaxf(g_cn * sqrtf(rn2), 1e-8f);
        float cos = fabsf(dot) / den;
        float lv = lam[v];
        g_ab[v] = make_float2(5.0f * lv * cos, 5.0f * (1.f - lv) * aff[v]);
    }
}

// ----------------- per-unique-concept weights + softmax -> fp16 P row
// No max subtraction needed: w <= 5*(1 + 1) = 10, exp(w) <= 2.3e4 (fp32-safe).
__global__ __launch_bounds__(256) void k_probs(const float* __restrict__ edge) {
    __shared__ float4 se4[Vn / 4];   // 40KB exp values
    __shared__ float red[9];
    int t = threadIdx.x;
    int cnt = g_cnt;

    for (int u = blockIdx.x; u < cnt; u += gridDim.x) {
        int c = g_uniq[u];
        const float4* em4 = (const float4*)(edge + (size_t)c * Vn);
        const float4* ab4 = (const float4*)g_ab;   // pairs: (a0,b0,a1,b1)

        float s = 0.f;
        for (int i = t; i < Vn / 4; i += 256) {
            float4 e = em4[i];
            float4 ab0 = ab4[2 * i];
            float4 ab1 = ab4[2 * i + 1];
            float w0 = e.x > 0.f ? fmaf(ab0.x, e.x, ab0.y) : 0.f;
            float w1 = e.y > 0.f ? fmaf(ab0.z, e.y, ab0.w) : 0.f;
            float w2 = e.z > 0.f ? fmaf(ab1.x, e.z, ab1.y) : 0.f;
            float w3 = e.w > 0.f ? fmaf(ab1.z, e.w, ab1.w) : 0.f;
            float4 ex;
            ex.x = __expf(w0); ex.y = __expf(w1);
            ex.z = __expf(w2); ex.w = __expf(w3);
            se4[i] = ex;
            s += (ex.x + ex.y) + (ex.z + ex.w);
        }
        #pragma unroll
        for (int o = 16; o > 0; o >>= 1) s += __shfl_xor_sync(0xffffffffu, s, o);
        if ((t & 31) == 0) red[t >> 5] = s;
        __syncthreads();
        if (t < 32) {
            float x = (t < 8) ? red[t] : 0.f;
            #pragma unroll
            for (int o = 4; o > 0; o >>= 1) x += __shfl_xor_sync(0xffffffffu, x, o);
            if (t == 0) red[8] = x;
        }
        __syncthreads();
        float inv = 1.f / red[8];

        uint2* pr = (uint2*)(g_P + (size_t)u * KPn);
        for (int i = t; i < Vn / 4; i += 256) {
            float4 ex = se4[i];
            __half2 h0 = __floats2half2_rn(ex.x * inv, ex.y * inv);
            __half2 h1 = __floats2half2_rn(ex.z * inv, ex.w * inv);
            uint2 pk;
            pk.x = *(unsigned*)&h0;
            pk.y = *(unsigned*)&h1;
            pr[i] = pk;
        }
        __syncthreads();   // red[] reuse safety for next u
    }
}

// ---------------------------------------------------------------- GEMM
// C[cnt,320] = P[cnt,10016]f16 @ W16[10016,320]f16, fp32 acc.
// Persistent CTAs; tile 128x64; 8 warps (4x2), warp tile 32x32;
// 3-stage cp.async pipeline, k-tile 32; mma m16n8k16.
__device__ __forceinline__ void cpa16(void* s, const void* g) {
    unsigned a = (unsigned)__cvta_generic_to_shared(s);
    asm volatile("cp.async.ca.shared.global [%0], [%1], 16;\n" :: "r"(a), "l"(g));
}

__global__ __launch_bounds__(256) void k_gemm() {
    __shared__ __half As[3][128][40];   // pad 40: conflict-free ldmatrix
    __shared__ __half Bs[3][32][72];    // pad 72
    int cnt = g_cnt;
    int mtiles = (cnt + 127) >> 7;
    int ntiles = mtiles * (NPn / 64);
    int t = threadIdx.x;
    int lane = t & 31, wid = t >> 5;
    int wm = (wid >> 1) * 32, wn = (wid & 1) * 32;
    int arow = t >> 1, acol = (t & 1) * 16;
    int brow = t >> 3, bcol = (t & 7) * 8;
    const int KT = KPn / 32;   // 313

    for (int tile = blockIdx.x; tile < ntiles; tile += gridDim.x) {
        int gm0 = (tile / (NPn / 64)) << 7;
        int n0  = (tile % (NPn / 64)) << 6;
        const __half* gA = g_P   + (size_t)(gm0 + arow) * KPn + acol;
        const __half* gB = g_W16 + (size_t)brow * NPn + n0 + bcol;

        float acc[2][4][4];
        #pragma unroll
        for (int i = 0; i < 2; i++)
            #pragma unroll
            for (int j = 0; j < 4; j++)
                #pragma unroll
                for (int k = 0; k < 4; k++) acc[i][j][k] = 0.f;

        #define LOADT(kt, s) {                                        \
            cpa16(&As[s][arow][acol],     gA + (size_t)(kt) * 32);    \
            cpa16(&As[s][arow][acol + 8], gA + (size_t)(kt) * 32 + 8);\
            cpa16(&Bs[s][brow][bcol], gB + (size_t)(kt) * 32 * NPn); }

        LOADT(0, 0);
        asm volatile("cp.async.commit_group;\n");
        LOADT(1, 1);
        asm volatile("cp.async.commit_group;\n");

        for (int kt = 0; kt < KT; kt++) {
            asm volatile("cp.async.wait_group 1;\n");
            __syncthreads();
            int kn = kt + 2;
            if (kn < KT) { LOADT(kn, kn % 3); }
            asm volatile("cp.async.commit_group;\n");   // always: keeps FIFO count

            int sb = kt % 3;
            #pragma unroll
            for (int kk = 0; kk < 32; kk += 16) {
                uint32_t a[2][4];
                #pragma unroll
                for (int mi = 0; mi < 2; mi++) {
                    unsigned ad = (unsigned)__cvta_generic_to_shared(
                        &As[sb][wm + mi * 16 + (lane & 15)][kk + (lane >> 4) * 8]);
                    asm volatile("ldmatrix.sync.aligned.m8n8.x4.shared.b16 {%0,%1,%2,%3}, [%4];\n"
                        : "=r"(a[mi][0]), "=r"(a[mi][1]), "=r"(a[mi][2]), "=r"(a[mi][3])
                        : "r"(ad));
                }
                uint32_t bb[4][2];
                #pragma unroll
                for (int nh = 0; nh < 2; nh++) {
                    unsigned ad = (unsigned)__cvta_generic_to_shared(
                        &Bs[sb][kk + (lane & 15)][wn + nh * 16 + (lane >> 4) * 8]);
                    asm volatile("ldmatrix.sync.aligned.m8n8.x4.trans.shared.b16 {%0,%1,%2,%3}, [%4];\n"
                        : "=r"(bb[nh * 2][0]), "=r"(bb[nh * 2][1]),
                          "=r"(bb[nh * 2 + 1][0]), "=r"(bb[nh * 2 + 1][1])
                        : "r"(ad));
                }
                #pragma unroll
                for (int mi = 0; mi < 2; mi++)
                    #pragma unroll
                    for (int nj = 0; nj < 4; nj++)
                        asm volatile("mma.sync.aligned.m16n8k16.row.col.f32.f16.f16.f32 "
                            "{%0,%1,%2,%3},{%4,%5,%6,%7},{%8,%9},{%0,%1,%2,%3};\n"
                            : "+f"(acc[mi][nj][0]), "+f"(acc[mi][nj][1]),
                              "+f"(acc[mi][nj][2]), "+f"(acc[mi][nj][3])
                            : "r"(a[mi][0]), "r"(a[mi][1]), "r"(a[mi][2]), "r"(a[mi][3]),
                              "r"(bb[nj][0]), "r"(bb[nj][1]));
            }
            __syncthreads();
        }
        #undef LOADT

        #pragma unroll
        for (int mi = 0; mi < 2; mi++) {
            int r0 = gm0 + wm + mi * 16 + (lane >> 2);
            #pragma unroll
            for (int nj = 0; nj < 4; nj++) {
                int cc = n0 + wn + nj * 8 + (lane & 3) * 2;
                *(float2*)&g_G[(size_t)r0 * NPn + cc] =
                    make_float2(acc[mi][nj][0], acc[mi][nj][1]);
                *(float2*)&g_G[(size_t)(r0 + 8) * NPn + cc] =
                    make_float2(acc[mi][nj][2], acc[mi][nj][3]);
            }
        }
        __syncthreads();   // smem reuse safety for next tile
    }
}

// ----------------------------------------------- gather + masked mean
__global__ void k_out(const int* __restrict__ clist,
                      const int* __restrict__ clen,
                      float* __restrict__ out) {
    int b = blockIdx.x;
    int d = threadIdx.x;
    if (d >= Dn) return;
    int len = clen[b];
    float acc = 0.f;
    for (int l = 0; l < len; l++) {
        int c = clist[b * Ln + l];
        int s = g_slot[c];
        acc += g_G[(size_t)s * NPn + d];
    }
    float den = (float)(len > 0 ? len : 1);
    out[b * Dn + d] = acc / den;
}

// ------------------------------------------------------------------ launch
extern "C" void kernel_launch(void* const* d_in, const int* in_sizes, int n_in,
                              void* d_out, int out_size) {
    const int*   clist = (const int*)d_in[0];
    const int*   clen  = (const int*)d_in[1];
    const float* embed = (const float*)d_in[2];
    const float* cw    = (const float*)d_in[3];
    const float* edge  = (const float*)d_in[4];
    const float* aff   = (const float*)d_in[5];
    const float* lam   = (const float*)d_in[6];
    float* out = (float*)d_out;

    k_reset<<<(Vn + 255) / 256, 256>>>();
    k_context<<<Bn, 320>>>(clist, clen, embed);
    k_finalize<<<1, 320>>>();
    k_dedup<<<Bn, Ln>>>(clist, clen);
    k_cosw<<<(Vn + 7) / 8, 256>>>(cw, aff, lam);
    k_probs<<<740, 256>>>(edge);
    k_gemm<<<148, 256>>>();
    k_out<<<Bn, 320>>>(clist, clen, out);
}